// round 11
// baseline (speedup 1.0000x reference)
#include <cuda_runtime.h>
#include <math.h>

#define BB 256
#define TT 512
#define II 128
#define HH 256
#define H2 512
#define H3 768
#define SMS 148
#define GRID 296
#define NTHR 256
#define GSTRIDE (GRID * NTHR)

typedef unsigned long long ull;

#define AP 66                 // As pitch (floats): 64 rows + 2 pad
#define WP 68                 // Ws pitch (floats): 64 cols + 4 pad
#define SA_BUF (32 * AP)
#define SW_BUF (32 * WP)

enum { EPI_RAW = 0, EPI_TANH = 2 };

// ---------------- persistent device scratch ----------------
__device__ float g_W1t[H2 * H2];
__device__ float g_W2t[H2 * H2];
__device__ float g_W3t[H2 * H2];
__device__ float g_WihT[HH * H3];
__device__ float g_WhhT[HH * H3];
__device__ float g_WcinT[II * HH];

__device__ float g_com[BB][H2];
__device__ float g_a1p[4][BB][H2];
__device__ float g_a2p[4][BB][H2];
__device__ float g_a3p[4][BB][H2];
__device__ float g_gip[2][BB][H3];
__device__ float g_ghp[2][BB][H3];
__device__ float g_c[BB][HH];
__device__ float g_h[BB][HH];
__device__ float g_n[BB];

// ---------------- hierarchical barriers (monotonic, replay-safe) ----------------
__device__ unsigned g_cntG[32 * 32];
__device__ unsigned g_cntL[16 * 32];
__device__ volatile unsigned g_genG;
__device__ volatile unsigned g_genL;
__device__ unsigned g_epochG, g_epochL;

__device__ __forceinline__ void barrier_G(unsigned k)
{
    __syncthreads();
    if (threadIdx.x == 0) {
        __threadfence();
        atomicAdd(&g_cntG[(blockIdx.x & 31) << 5], 1u);
        if (blockIdx.x == 0) {
            unsigned long long need = (unsigned long long)k * GRID;
            for (;;) {
                unsigned long long s = 0;
#pragma unroll
                for (int i = 0; i < 32; i++) s += ((volatile unsigned*)g_cntG)[i << 5];
                if (s >= need) break;
                __nanosleep(64);
            }
            __threadfence();
            g_genG = k;
        } else {
            while (g_genG < k) __nanosleep(96);
        }
        __threadfence();
    }
    __syncthreads();
}

__device__ __forceinline__ void barrier_L(unsigned k)    // bids 0..127 only
{
    __syncthreads();
    if (threadIdx.x == 0) {
        __threadfence();
        atomicAdd(&g_cntL[(blockIdx.x & 15) << 5], 1u);
        if (blockIdx.x == 0) {
            unsigned long long need = (unsigned long long)k * 128u;
            for (;;) {
                unsigned long long s = 0;
#pragma unroll
                for (int i = 0; i < 16; i++) s += ((volatile unsigned*)g_cntL)[i << 5];
                if (s >= need) break;
                __nanosleep(32);
            }
            __threadfence();
            g_genL = k;
        } else {
            while (g_genL < k) __nanosleep(64);
        }
        __threadfence();
    }
    __syncthreads();
}

__device__ __forceinline__ float sigf(float x) { return 1.f / (1.f + expf(-x)); }

__device__ __forceinline__ ull pack2(float x, float y) {
    ull r; asm("mov.b64 %0,{%1,%2};" : "=l"(r) : "f"(x), "f"(y)); return r;
}
__device__ __forceinline__ void unpack2(ull v, float& x, float& y) {
    asm("mov.b64 {%0,%1},%2;" : "=f"(x), "=f"(y) : "l"(v));
}
__device__ __forceinline__ void fma2(ull& d, ull a, ull b) {
    asm("fma.rn.f32x2 %0, %1, %2, %0;" : "+l"(d) : "l"(a), "l"(b));
}

// -------------------------------------------------------------------------
// 64x64 output tile, K=128 (4 k-tiles), 256 threads, per-thread 2x8.
// Inner loop per kk: LDS.64 (A pair) + 2x LDS.128 (W) + 8 FFMA2.
// NSRC=4: A = relu(sum of 4 partials + Ab) computed in the prefetch.
// -------------------------------------------------------------------------
template<int EPI, int NSRC>
__device__ __noinline__ void gemm64(
    const float* __restrict__ A0, size_t srcStride, const float* __restrict__ Ab,
    int lda, int koff,
    const float* __restrict__ Wt, int ldw,
    const float* __restrict__ bias,
    float* __restrict__ C, int ldc,
    int rowBase, int colBase,
    float* __restrict__ As, float* __restrict__ Ws)
{
    const int tid  = threadIdx.x;
    const int tx8  = (tid & 7) * 8;       // compute: col oct
    const int ty2  = (tid >> 3) * 2;      // compute: row pair (0..62)
    const int arow = tid >> 2;            // A loader: row 0..63
    const int akq  = tid & 3;             // A loader: k-oct
    const int wkk  = tid >> 3;            // W loader: k 0..31
    const int wc8  = (tid & 7) * 8;       // W loader: col oct

    ull c00 = 0, c01 = 0, c02 = 0, c03 = 0;
    ull c10 = 0, c11 = 0, c12 = 0, c13 = 0;
    float4 va0, va1, vw0, vw1;

#define LOAD_T(kt)                                                             \
    {                                                                          \
        int kg = koff + (kt) * 32 + akq * 8;                                   \
        const float* ap = A0 + (size_t)(rowBase + arow) * lda + kg;            \
        va0 = *(const float4*)ap;                                              \
        va1 = *(const float4*)(ap + 4);                                        \
        if (NSRC == 4) {                                                       \
            _Pragma("unroll")                                                  \
            for (int pp = 1; pp < 4; pp++) {                                   \
                const float* bp = ap + pp * srcStride;                         \
                float4 u0 = *(const float4*)bp;                                \
                float4 u1 = *(const float4*)(bp + 4);                          \
                va0.x += u0.x; va0.y += u0.y; va0.z += u0.z; va0.w += u0.w;    \
                va1.x += u1.x; va1.y += u1.y; va1.z += u1.z; va1.w += u1.w;    \
            }                                                                  \
            float4 k0 = *(const float4*)(Ab + kg);                             \
            float4 k1 = *(const float4*)(Ab + kg + 4);                         \
            va0.x = fmaxf(va0.x + k0.x, 0.f);                                  \
            va0.y = fmaxf(va0.y + k0.y, 0.f);                                  \
            va0.z = fmaxf(va0.z + k0.z, 0.f);                                  \
            va0.w = fmaxf(va0.w + k0.w, 0.f);                                  \
            va1.x = fmaxf(va1.x + k1.x, 0.f);                                  \
            va1.y = fmaxf(va1.y + k1.y, 0.f);                                  \
            va1.z = fmaxf(va1.z + k1.z, 0.f);                                  \
            va1.w = fmaxf(va1.w + k1.w, 0.f);                                  \
        }                                                                      \
        const float* wp = Wt + (size_t)(koff + (kt) * 32 + wkk) * ldw          \
                          + colBase + wc8;                                     \
        vw0 = *(const float4*)wp;                                              \
        vw1 = *(const float4*)(wp + 4);                                        \
    }

#define STORE_T(bi)                                                            \
    {                                                                          \
        float* as = As + (bi) * SA_BUF;                                        \
        float* ws = Ws + (bi) * SW_BUF;                                        \
        as[(akq * 8 + 0) * AP + arow] = va0.x;                                 \
        as[(akq * 8 + 1) * AP + arow] = va0.y;                                 \
        as[(akq * 8 + 2) * AP + arow] = va0.z;                                 \
        as[(akq * 8 + 3) * AP + arow] = va0.w;                                 \
        as[(akq * 8 + 4) * AP + arow] = va1.x;                                 \
        as[(akq * 8 + 5) * AP + arow] = va1.y;                                 \
        as[(akq * 8 + 6) * AP + arow] = va1.z;                                 \
        as[(akq * 8 + 7) * AP + arow] = va1.w;                                 \
        *(float4*)(ws + wkk * WP + wc8)     = vw0;                             \
        *(float4*)(ws + wkk * WP + wc8 + 4) = vw1;                             \
    }

    LOAD_T(0);
    STORE_T(0);
    __syncthreads();

#pragma unroll
    for (int kt = 0; kt < 4; kt++) {
        if (kt < 3) LOAD_T(kt + 1);
        {
            const float* as = As + (kt & 1) * SA_BUF;
            const float* ws = Ws + (kt & 1) * SW_BUF;
#pragma unroll
            for (int kk = 0; kk < 32; kk++) {
                ull a01 = *(const ull*)(as + kk * AP + ty2);
                float a0, a1;
                unpack2(a01, a0, a1);
                ull d0 = pack2(a0, a0);
                ull d1 = pack2(a1, a1);
                ulonglong2 wA = *(const ulonglong2*)(ws + kk * WP + tx8);
                ulonglong2 wB = *(const ulonglong2*)(ws + kk * WP + tx8 + 4);
                fma2(c00, d0, wA.x);
                fma2(c01, d0, wA.y);
                fma2(c02, d0, wB.x);
                fma2(c03, d0, wB.y);
                fma2(c10, d1, wA.x);
                fma2(c11, d1, wA.y);
                fma2(c12, d1, wB.x);
                fma2(c13, d1, wB.y);
            }
        }
        if (kt < 3) STORE_T((kt + 1) & 1);
        __syncthreads();
    }
#undef LOAD_T
#undef STORE_T

    float* p0 = C + (size_t)(rowBase + ty2) * ldc + colBase + tx8;
    float* p1 = p0 + ldc;
    if (EPI == EPI_RAW) {
        ulonglong2 v;
        v.x = c00; v.y = c01; *(ulonglong2*)p0 = v;
        v.x = c02; v.y = c03; *(ulonglong2*)(p0 + 4) = v;
        v.x = c10; v.y = c11; *(ulonglong2*)p1 = v;
        v.x = c12; v.y = c13; *(ulonglong2*)(p1 + 4) = v;
    } else {
        float4 o0, o1, o2, o3;
        unpack2(c00, o0.x, o0.y); unpack2(c01, o0.z, o0.w);
        unpack2(c02, o1.x, o1.y); unpack2(c03, o1.z, o1.w);
        unpack2(c10, o2.x, o2.y); unpack2(c11, o2.z, o2.w);
        unpack2(c12, o3.x, o3.y); unpack2(c13, o3.z, o3.w);
        float4 b0 = *(const float4*)(bias + colBase + tx8);
        float4 b1v = *(const float4*)(bias + colBase + tx8 + 4);
        o0.x = tanhf(o0.x + b0.x); o0.y = tanhf(o0.y + b0.y);
        o0.z = tanhf(o0.z + b0.z); o0.w = tanhf(o0.w + b0.w);
        o1.x = tanhf(o1.x + b1v.x); o1.y = tanhf(o1.y + b1v.y);
        o1.z = tanhf(o1.z + b1v.z); o1.w = tanhf(o1.w + b1v.w);
        o2.x = tanhf(o2.x + b0.x); o2.y = tanhf(o2.y + b0.y);
        o2.z = tanhf(o2.z + b0.z); o2.w = tanhf(o2.w + b0.w);
        o3.x = tanhf(o3.x + b1v.x); o3.y = tanhf(o3.y + b1v.y);
        o3.z = tanhf(o3.z + b1v.z); o3.w = tanhf(o3.w + b1v.w);
        *(float4*)p0 = o0; *(float4*)(p0 + 4) = o1;
        *(float4*)p1 = o2; *(float4*)(p1 + 4) = o3;
    }
}

// MLP job j in [0,128): rt(0..3) x ct(0..7) x kh(0..3), K-range kh*128
__device__ __forceinline__ void mlp_job(int ph, int j, const float* b1,
                                        const float* b2, float* As, float* Ws)
{
    int rt = j >> 5, ct = (j >> 2) & 7, kh = j & 3;
    int rb = rt * 64, cb = ct * 64, ko = kh * 128;
    if (ph == 0)
        gemm64<EPI_RAW, 1>(&g_com[0][0], 0, 0, H2, ko, g_W1t, H2, 0,
                           &g_a1p[kh][0][0], H2, rb, cb, As, Ws);
    else if (ph == 1)
        gemm64<EPI_RAW, 4>(&g_a1p[0][0][0], (size_t)BB * H2, b1, H2, ko,
                           g_W2t, H2, 0, &g_a2p[kh][0][0], H2, rb, cb, As, Ws);
    else
        gemm64<EPI_RAW, 4>(&g_a2p[0][0][0], (size_t)BB * H2, b2, H2, ko,
                           g_W3t, H2, 0, &g_a3p[kh][0][0], H2, rb, cb, As, Ws);
}

// gate job g in [0,192): g<96 gi else gh; q -> rt(0..3) x ct(0..11) x kh(0..1)
__device__ __forceinline__ void gate_job(int g, float* As, float* Ws)
{
    bool is_gi = g < 96;
    int q = is_gi ? g : g - 96;
    int rt = q / 24, r2 = q % 24, ct = r2 >> 1, kh = r2 & 1;
    int rb = rt * 64, cb = ct * 64, ko = kh * 128;
    if (is_gi)
        gemm64<EPI_RAW, 1>(&g_c[0][0], 0, 0, HH, ko, g_WihT, H3, 0,
                           &g_gip[kh][0][0], H3, rb, cb, As, Ws);
    else
        gemm64<EPI_RAW, 1>(&g_h[0][0], 0, 0, HH, ko, g_WhhT, H3, 0,
                           &g_ghp[kh][0][0], H3, rb, cb, As, Ws);
}

// =========================== persistent megakernel ===========================
__global__ void __launch_bounds__(NTHR, 2)
rnn_persistent(const float* __restrict__ input, const float* __restrict__ noise,
               const float* __restrict__ Wcin, const float* __restrict__ bcin,
               const float* __restrict__ W1, const float* __restrict__ b1,
               const float* __restrict__ W2, const float* __restrict__ b2,
               const float* __restrict__ W3, const float* __restrict__ b3,
               const float* __restrict__ W4, const float* __restrict__ b4,
               const float* __restrict__ Wih, const float* __restrict__ Whh,
               const float* __restrict__ bih, const float* __restrict__ bhh,
               float* __restrict__ outC, float* __restrict__ outH,
               float* __restrict__ outF)
{
    __shared__ __align__(16) float sAs[2 * SA_BUF];
    __shared__ __align__(16) float sWs[2 * SW_BUF];
    __shared__ float su[16];

    const int bid = blockIdx.x;
    const int tid = threadIdx.x;
    const int gt  = bid * NTHR + tid;
    const int sm  = bid % SMS;
    const int slot = bid / SMS;

    unsigned kG = g_epochG;
    unsigned kL = g_epochL;

    // -------- weight transposes --------
    for (int i = gt; i < H2 * H2; i += GSTRIDE) {
        int k = i / H2, n = i % H2;
        g_W1t[i] = W1[(size_t)n * H2 + k];
        g_W2t[i] = W2[(size_t)n * H2 + k];
        g_W3t[i] = W3[(size_t)n * H2 + k];
    }
    for (int i = gt; i < HH * H3; i += GSTRIDE) {
        int k = i / H3, n = i % H3;
        g_WihT[i] = Wih[(size_t)n * HH + k];
        g_WhhT[i] = Whh[(size_t)n * HH + k];
    }
    for (int i = gt; i < II * HH; i += GSTRIDE) {
        int k = i / HH, n = i % HH;
        g_WcinT[i] = Wcin[(size_t)n * II + k];
    }
    barrier_G(++kG);

    // -------- prologue: c_in = tanh(x @ Wcin^T) -> c_concat (row = b*T+t) --------
    for (int j = bid; j < 8192; j += GRID) {
        int rt = j >> 2, ct = j & 3;
        gemm64<EPI_TANH, 1>(input, 0, 0, II, 0, g_WcinT, HH, bcin,
                            outC, HH, rt * 64, ct * 64, sAs, sWs);
    }
    barrier_G(++kG);

    // -------- init state --------
    if (bid < BB) {
        int b = bid;
        g_c[b][tid] = 0.f;
        g_h[b][tid] = 0.f;
        g_com[b][tid] = 0.f;
        g_com[b][HH + tid] = outC[(size_t)b * TT * HH + tid];
        if (tid == 0) g_n[b] = 0.f;
    }
    barrier_G(++kG);

    // -------- recurrent loop --------
    for (int t = 0; t < TT; t++) {
        if (bid < 128) {
            mlp_job(0, bid, b1, b2, sAs, sWs);
            barrier_L(++kL);
            mlp_job(1, bid, b1, b2, sAs, sWs);
            barrier_L(++kL);
            mlp_job(2, bid, b1, b2, sAs, sWs);
        } else {
            kL += 2;
            if (sm >= 128) {                      // SMs 128..147, both slots: 2 serial
                int base = (slot == 0 ? 0 : 40) + (sm - 128) * 2;
                gate_job(base, sAs, sWs);
                gate_job(base + 1, sAs, sWs);
            } else if (slot == 1 && sm < 112) {   // slot-1 CTAs on SMs 0..111
                gate_job(80 + sm, sAs, sWs);
            }
        }
        barrier_G(++kG);

        // -------- phase U --------
        if (bid < BB) {
            int b = bid;
            float part = 0.f;
#pragma unroll
            for (int q = 0; q < 2; q++) {
                int k = tid + q * NTHR;
                float v = g_a3p[0][b][k] + g_a3p[1][b][k] + g_a3p[2][b][k]
                        + g_a3p[3][b][k] + b3[k];
                part += fmaxf(v, 0.f) * W4[k];
            }
#pragma unroll
            for (int sh = 16; sh > 0; sh >>= 1)
                part += __shfl_down_sync(0xffffffffu, part, sh);
            if ((tid & 31) == 0) su[tid >> 5] = part;
            __syncthreads();
            if (tid == 0) {
                float logit = b4[0];
#pragma unroll
                for (int w = 0; w < 8; w++) logit += su[w];
                float u = noise[(size_t)t * BB + b];
                float logistic = logf(u) - log1pf(-u);
                float a = sigf((logit + logistic) * 10.f);   // / TEMP
                float nold = g_n[b];
                su[8] = a;
                su[9] = nold;
                g_n[b] = nold * (1.f - a) + 1.f;
            }
            __syncthreads();
            float alpha = su[8], nold = su[9];
            float nnew = nold * (1.f - alpha) + 1.f;
            int jj = tid;
            float c = g_c[b][jj], h = g_h[b][jj];
            float cin = outC[(size_t)b * TT * HH + (size_t)t * HH + jj];
            float gir = g_gip[0][b][jj] + g_gip[1][b][jj] + bih[jj];
            float ghr = g_ghp[0][b][jj] + g_ghp[1][b][jj] + bhh[jj];
            float giz = g_gip[0][b][HH + jj] + g_gip[1][b][HH + jj] + bih[HH + jj];
            float ghz = g_ghp[0][b][HH + jj] + g_ghp[1][b][HH + jj] + bhh[HH + jj];
            float gin = g_gip[0][b][2 * HH + jj] + g_gip[1][b][2 * HH + jj] + bih[2 * HH + jj];
            float ghn = g_ghp[0][b][2 * HH + jj] + g_ghp[1][b][2 * HH + jj] + bhh[2 * HH + jj];
            float r  = sigf(gir + ghr);
            float z  = sigf(giz + ghz);
            float ng = tanhf(gin + r * ghn);
            float hcand = (1.f - z) * ng + z * h;
            float hnew = h * (1.f - alpha) + alpha * hcand;
            float cnew = (c * nold * (1.f - alpha) + cin) / nnew;
            g_c[b][jj] = cnew;
            g_h[b][jj] = hnew;
            outH[(size_t)b * TT * HH + (size_t)t * HH + jj] = hnew;
            g_com[b][jj] = cnew;
            if (t + 1 < TT)
                g_com[b][HH + jj] = outC[(size_t)b * TT * HH + (size_t)(t + 1) * HH + jj];
        }
        barrier_G(++kG);
    }

    // -------- epilogue: h_final = gru_cell(c_T, h_T) --------
    if (bid < 192) gate_job(bid, sAs, sWs);
    barrier_G(++kG);
    if (bid < BB) {
        int b = bid, jj = tid;
        float h = g_h[b][jj];
        float gir = g_gip[0][b][jj] + g_gip[1][b][jj] + bih[jj];
        float ghr = g_ghp[0][b][jj] + g_ghp[1][b][jj] + bhh[jj];
        float giz = g_gip[0][b][HH + jj] + g_gip[1][b][HH + jj] + bih[HH + jj];
        float ghz = g_ghp[0][b][HH + jj] + g_ghp[1][b][HH + jj] + bhh[HH + jj];
        float gin = g_gip[0][b][2 * HH + jj] + g_gip[1][b][2 * HH + jj] + bih[2 * HH + jj];
        float ghn = g_ghp[0][b][2 * HH + jj] + g_ghp[1][b][2 * HH + jj] + bhh[2 * HH + jj];
        float r  = sigf(gir + ghr);
        float z  = sigf(giz + ghz);
        float ng = tanhf(gin + r * ghn);
        outF[(size_t)b * HH + jj] = (1.f - z) * ng + z * h;
    }

    if (bid == 0 && tid == 0) {
        g_epochG = kG;
        g_epochL = kL;
    }
}

extern "C" void kernel_launch(void* const* d_in, const int* in_sizes, int n_in,
                              void* d_out, int out_size)
{
    const float* input = (const float*)d_in[0];
    const float* noise = (const float*)d_in[1];
    const float* Wcin  = (const float*)d_in[2];
    const float* bcin  = (const float*)d_in[3];
    const float* W1    = (const float*)d_in[4];
    const float* b1    = (const float*)d_in[5];
    const float* W2    = (const float*)d_in[6];
    const float* b2    = (const float*)d_in[7];
    const float* W3    = (const float*)d_in[8];
    const float* b3    = (const float*)d_in[9];
    const float* W4    = (const float*)d_in[10];
    const float* b4    = (const float*)d_in[11];
    const float* Wih   = (const float*)d_in[12];
    const float* Whh   = (const float*)d_in[13];
    const float* bih   = (const float*)d_in[14];
    const float* bhh   = (const float*)d_in[15];

    float* outC = (float*)d_out;                   // c_concat [B,T,H]
    float* outH = outC + (size_t)BB * TT * HH;     // h_concat [B,T,H]
    float* outF = outH + (size_t)BB * TT * HH;     // h_final  [B,H]

    rnn_persistent<<<GRID, NTHR>>>(input, noise, Wcin, bcin, W1, b1, W2, b2,
                                   W3, b3, W4, b4, Wih, Whh, bih, bhh,
                                   outC, outH, outF);
}

// round 12
// speedup vs baseline: 1.0421x; 1.0421x over previous
#include <cuda_runtime.h>
#include <math.h>

#define BB 256
#define TT 512
#define II 128
#define HH 256
#define H2 512
#define H3 768
#define SMS 148
#define GRID 444          // 3 CTAs per SM
#define NTHR 128
#define GSTRIDE (GRID * NTHR)

typedef unsigned long long ull;

#define ASP 36            // As row pitch (floats)
#define WSP 68            // Ws row pitch (floats)
#define SA_BUF (32 * ASP)
#define SW_BUF (32 * WSP)

enum { EPI_RAW = 0, EPI_BIAS = 1, EPI_TANH = 2 };

// ---------------- persistent device scratch (no allocations) ----------------
__device__ float g_W1t[H2 * H2];     // transposed weights: Wt[k][n] = W[n][k]
__device__ float g_W2t[H2 * H2];
__device__ float g_W3t[H2 * H2];
__device__ float g_WihT[HH * H3];
__device__ float g_WhhT[HH * H3];
__device__ float g_WcinT[II * HH];

__device__ float g_com[BB][H2];      // [c | c_in_t]
__device__ float g_a1p[2][BB][H2];   // MLP K-split partials
__device__ float g_a2p[2][BB][H2];
__device__ float g_a3p[2][BB][H2];
__device__ float g_gip[2][BB][H3];   // gate K-split partials (no bias)
__device__ float g_ghp[2][BB][H3];
__device__ float g_c[BB][HH];
__device__ float g_h[BB][HH];
__device__ float g_n[BB];

// ---------------- hierarchical barriers (monotonic, replay-safe) ----------------
__device__ unsigned g_cntG[32 * 32];
__device__ unsigned g_cntL[16 * 32];
__device__ volatile unsigned g_genG;
__device__ volatile unsigned g_genL;
__device__ unsigned g_epochG, g_epochL;

__device__ __forceinline__ void barrier_G(unsigned k)
{
    __syncthreads();
    if (threadIdx.x == 0) {
        __threadfence();
        atomicAdd(&g_cntG[(blockIdx.x & 31) << 5], 1u);
        if (blockIdx.x == 0) {
            unsigned long long need = (unsigned long long)k * GRID;
            for (;;) {
                unsigned long long s = 0;
#pragma unroll
                for (int i = 0; i < 32; i++)
                    s += ((volatile unsigned*)g_cntG)[i << 5];
                if (s >= need) break;
                __nanosleep(64);
            }
            __threadfence();
            g_genG = k;
        } else {
            while (g_genG < k) __nanosleep(96);
        }
        __threadfence();
    }
    __syncthreads();
}

// light barrier: only bids 0..127 participate
__device__ __forceinline__ void barrier_L(unsigned k)
{
    __syncthreads();
    if (threadIdx.x == 0) {
        __threadfence();
        atomicAdd(&g_cntL[(blockIdx.x & 15) << 5], 1u);
        if (blockIdx.x == 0) {
            unsigned long long need = (unsigned long long)k * 128u;
            for (;;) {
                unsigned long long s = 0;
#pragma unroll
                for (int i = 0; i < 16; i++)
                    s += ((volatile unsigned*)g_cntL)[i << 5];
                if (s >= need) break;
                __nanosleep(32);
            }
            __threadfence();
            g_genL = k;
        } else {
            while (g_genL < k) __nanosleep(64);
        }
        __threadfence();
    }
    __syncthreads();
}

__device__ __forceinline__ float sigf(float x) { return 1.f / (1.f + expf(-x)); }

// ---------------- packed f32x2 helpers ----------------
__device__ __forceinline__ ull pack2(float x, float y) {
    ull r; asm("mov.b64 %0,{%1,%2};" : "=l"(r) : "f"(x), "f"(y)); return r;
}
__device__ __forceinline__ void unpack2(ull v, float& x, float& y) {
    asm("mov.b64 {%0,%1},%2;" : "=f"(x), "=f"(y) : "l"(v));
}
__device__ __forceinline__ void fma2(ull& d, ull a, ull b) {
    asm("fma.rn.f32x2 %0, %1, %2, %0;" : "+l"(d) : "l"(a), "l"(b));
}

// -------------------------------------------------------------------------
// One 32x64 output tile of C = epi(A @ Wt), 128 threads, per-thread 2x8.
// (R6/R9-proven: per kk = LDS.64 + 2xLDS.128 + 8 FFMA2, conflict-free)
// -------------------------------------------------------------------------
template<int EPI, bool COMBINE>
__device__ __noinline__ void gemm32x64(
    const float* __restrict__ A0, const float* __restrict__ A1,
    const float* __restrict__ Ab, int lda, int koff,
    const float* __restrict__ Wt, int ldw,
    const float* __restrict__ bias,
    float* __restrict__ C, int ldc,
    int rowBase, int colBase, int nkt,
    float* __restrict__ As, float* __restrict__ Ws)
{
    const int tid  = threadIdx.x;
    const int tx4  = (tid & 7) * 4;        // col block offset
    const int ty2  = (tid >> 3) * 2;       // row pair
    const int arow = tid >> 3;             // A-stage row (and +16)
    const int akq  = tid & 7;              // A-stage k-quad
    const int wkk  = tid >> 4;             // W-stage kk (0..7, +8,+16,+24)
    const int wc4  = (tid & 15) * 4;       // W-stage col quad

    ull c00 = 0, c01 = 0, c02 = 0, c03 = 0;
    ull c10 = 0, c11 = 0, c12 = 0, c13 = 0;
    float4 va0, va1, vw0, vw1, vw2, vw3;

#define LOAD_T(kt)                                                              \
    {                                                                           \
        int kg = koff + (kt) * 32;                                              \
        const float* ap = A0 + (size_t)(rowBase + arow) * lda + kg + akq * 4;   \
        va0 = *(const float4*)ap;                                               \
        va1 = *(const float4*)(ap + 16 * (size_t)lda);                          \
        if (COMBINE) {                                                          \
            const float* a1p = A1 + (size_t)(rowBase + arow) * lda + kg + akq * 4; \
            float4 u0 = *(const float4*)a1p;                                    \
            float4 u1 = *(const float4*)(a1p + 16 * (size_t)lda);               \
            float4 bb = *(const float4*)(Ab + kg + akq * 4);                    \
            va0.x = fmaxf(va0.x + u0.x + bb.x, 0.f);                            \
            va0.y = fmaxf(va0.y + u0.y + bb.y, 0.f);                            \
            va0.z = fmaxf(va0.z + u0.z + bb.z, 0.f);                            \
            va0.w = fmaxf(va0.w + u0.w + bb.w, 0.f);                            \
            va1.x = fmaxf(va1.x + u1.x + bb.x, 0.f);                            \
            va1.y = fmaxf(va1.y + u1.y + bb.y, 0.f);                            \
            va1.z = fmaxf(va1.z + u1.z + bb.z, 0.f);                            \
            va1.w = fmaxf(va1.w + u1.w + bb.w, 0.f);                            \
        }                                                                       \
        const float* wp = Wt + (size_t)(kg + wkk) * ldw + colBase + wc4;        \
        vw0 = *(const float4*)wp;                                               \
        vw1 = *(const float4*)(wp + 8  * (size_t)ldw);                          \
        vw2 = *(const float4*)(wp + 16 * (size_t)ldw);                          \
        vw3 = *(const float4*)(wp + 24 * (size_t)ldw);                          \
    }

#define STORE_T(bi)                                                             \
    {                                                                           \
        float* as = As + (bi) * SA_BUF;                                         \
        float* ws = Ws + (bi) * SW_BUF;                                         \
        as[(akq * 4 + 0) * ASP + arow]      = va0.x;                            \
        as[(akq * 4 + 1) * ASP + arow]      = va0.y;                            \
        as[(akq * 4 + 2) * ASP + arow]      = va0.z;                            \
        as[(akq * 4 + 3) * ASP + arow]      = va0.w;                            \
        as[(akq * 4 + 0) * ASP + arow + 16] = va1.x;                            \
        as[(akq * 4 + 1) * ASP + arow + 16] = va1.y;                            \
        as[(akq * 4 + 2) * ASP + arow + 16] = va1.z;                            \
        as[(akq * 4 + 3) * ASP + arow + 16] = va1.w;                            \
        *(float4*)(ws + (wkk + 0)  * WSP + wc4) = vw0;                          \
        *(float4*)(ws + (wkk + 8)  * WSP + wc4) = vw1;                          \
        *(float4*)(ws + (wkk + 16) * WSP + wc4) = vw2;                          \
        *(float4*)(ws + (wkk + 24) * WSP + wc4) = vw3;                          \
    }

    LOAD_T(0);
    STORE_T(0);
    __syncthreads();

    for (int kt = 0; kt < nkt; kt++) {
        if (kt + 1 < nkt) LOAD_T(kt + 1);
        {
            const float* as = As + (kt & 1) * SA_BUF;
            const float* ws = Ws + (kt & 1) * SW_BUF;
#pragma unroll
            for (int kk = 0; kk < 32; kk++) {
                ull a01 = *(const ull*)(as + kk * ASP + ty2);
                float a0, a1;
                unpack2(a01, a0, a1);
                ull d0 = pack2(a0, a0);
                ull d1 = pack2(a1, a1);
                ulonglong2 wA = *(const ulonglong2*)(ws + kk * WSP + tx4);
                ulonglong2 wB = *(const ulonglong2*)(ws + kk * WSP + 32 + tx4);
                fma2(c00, d0, wA.x);
                fma2(c01, d0, wA.y);
                fma2(c02, d0, wB.x);
                fma2(c03, d0, wB.y);
                fma2(c10, d1, wA.x);
                fma2(c11, d1, wA.y);
                fma2(c12, d1, wB.x);
                fma2(c13, d1, wB.y);
            }
        }
        if (kt + 1 < nkt) STORE_T((kt + 1) & 1);
        __syncthreads();
    }
#undef LOAD_T
#undef STORE_T

    float4 o00, o01, o10, o11;
    unpack2(c00, o00.x, o00.y); unpack2(c01, o00.z, o00.w);
    unpack2(c02, o01.x, o01.y); unpack2(c03, o01.z, o01.w);
    unpack2(c10, o10.x, o10.y); unpack2(c11, o10.z, o10.w);
    unpack2(c12, o11.x, o11.y); unpack2(c13, o11.z, o11.w);
    if (EPI != EPI_RAW) {
        float4 b0 = *(const float4*)(bias + colBase + tx4);
        float4 b1 = *(const float4*)(bias + colBase + 32 + tx4);
        o00.x += b0.x; o00.y += b0.y; o00.z += b0.z; o00.w += b0.w;
        o10.x += b0.x; o10.y += b0.y; o10.z += b0.z; o10.w += b0.w;
        o01.x += b1.x; o01.y += b1.y; o01.z += b1.z; o01.w += b1.w;
        o11.x += b1.x; o11.y += b1.y; o11.z += b1.z; o11.w += b1.w;
        if (EPI == EPI_TANH) {
            o00.x = tanhf(o00.x); o00.y = tanhf(o00.y); o00.z = tanhf(o00.z); o00.w = tanhf(o00.w);
            o01.x = tanhf(o01.x); o01.y = tanhf(o01.y); o01.z = tanhf(o01.z); o01.w = tanhf(o01.w);
            o10.x = tanhf(o10.x); o10.y = tanhf(o10.y); o10.z = tanhf(o10.z); o10.w = tanhf(o10.w);
            o11.x = tanhf(o11.x); o11.y = tanhf(o11.y); o11.z = tanhf(o11.z); o11.w = tanhf(o11.w);
        }
    }
    float* crow0 = C + (size_t)(rowBase + ty2) * ldc + colBase;
    float* crow1 = crow0 + ldc;
    *(float4*)(crow0 + tx4)      = o00;
    *(float4*)(crow0 + 32 + tx4) = o01;
    *(float4*)(crow1 + tx4)      = o10;
    *(float4*)(crow1 + 32 + tx4) = o11;
}

// gate half-job: g in [0,384). g<192 -> gi else gh.
// q -> rt(0..7) x ct(0..11) x kh(0..1); nkt=4, K-range kh*128.
__device__ __forceinline__ void gate_job(int g, float* As, float* Ws)
{
    bool is_gi = g < 192;
    int q = is_gi ? g : g - 192;
    int rt = q / 24, rem = q % 24, ct = rem >> 1, kh = rem & 1;
    int rb = rt * 32, cb = ct * 64, ko = kh * 128;
    if (is_gi)
        gemm32x64<EPI_RAW, false>(&g_c[0][0], 0, 0, HH, ko, g_WihT, H3, 0,
                                  &g_gip[kh][0][0], H3, rb, cb, 4, As, Ws);
    else
        gemm32x64<EPI_RAW, false>(&g_h[0][0], 0, 0, HH, ko, g_WhhT, H3, 0,
                                  &g_ghp[kh][0][0], H3, rb, cb, 4, As, Ws);
}

// MLP job (one per slot-0 CTA per phase): j in [0,128), K-split 2, nkt=8
__device__ __forceinline__ void do_a(int ph, int j, const float* b1,
                                     const float* b2, float* As, float* Ws)
{
    int rt = j >> 4, kh = (j >> 3) & 1, ct = j & 7;
    int rb = rt * 32, cb = ct * 64, ko = kh * 256;
    if (ph == 0)
        gemm32x64<EPI_RAW, false>(&g_com[0][0], 0, 0, H2, ko, g_W1t, H2, 0,
                                  &g_a1p[kh][0][0], H2, rb, cb, 8, As, Ws);
    else if (ph == 1)
        gemm32x64<EPI_RAW, true>(&g_a1p[0][0][0], &g_a1p[1][0][0], b1, H2, ko,
                                 g_W2t, H2, 0, &g_a2p[kh][0][0], H2, rb, cb, 8, As, Ws);
    else
        gemm32x64<EPI_RAW, true>(&g_a2p[0][0][0], &g_a2p[1][0][0], b2, H2, ko,
                                 g_W3t, H2, 0, &g_a3p[kh][0][0], H2, rb, cb, 8, As, Ws);
}

// =========================== persistent megakernel ===========================
__global__ void __launch_bounds__(NTHR, 3)
rnn_persistent(const float* __restrict__ input, const float* __restrict__ noise,
               const float* __restrict__ Wcin, const float* __restrict__ bcin,
               const float* __restrict__ W1, const float* __restrict__ b1,
               const float* __restrict__ W2, const float* __restrict__ b2,
               const float* __restrict__ W3, const float* __restrict__ b3,
               const float* __restrict__ W4, const float* __restrict__ b4,
               const float* __restrict__ Wih, const float* __restrict__ Whh,
               const float* __restrict__ bih, const float* __restrict__ bhh,
               float* __restrict__ outC, float* __restrict__ outH,
               float* __restrict__ outF)
{
    __shared__ __align__(16) float sAs[2 * SA_BUF];
    __shared__ __align__(16) float sWs[2 * SW_BUF];
    __shared__ float su[16];

    const int bid = blockIdx.x;
    const int tid = threadIdx.x;
    const int gt  = bid * NTHR + tid;
    const int sm  = bid % SMS;
    const int sl  = bid / SMS;

    unsigned kG = g_epochG;
    unsigned kL = g_epochL;

    // -------- weight transposes (once per launch) --------
    for (int i = gt; i < H2 * H2; i += GSTRIDE) {
        int k = i / H2, n = i % H2;
        g_W1t[i] = W1[(size_t)n * H2 + k];
        g_W2t[i] = W2[(size_t)n * H2 + k];
        g_W3t[i] = W3[(size_t)n * H2 + k];
    }
    for (int i = gt; i < HH * H3; i += GSTRIDE) {
        int k = i / H3, n = i % H3;
        g_WihT[i] = Wih[(size_t)n * HH + k];
        g_WhhT[i] = Whh[(size_t)n * HH + k];
    }
    for (int i = gt; i < II * HH; i += GSTRIDE) {
        int k = i / HH, n = i % HH;
        g_WcinT[i] = Wcin[(size_t)n * II + k];
    }
    barrier_G(++kG);

    // -------- prologue: c_in = tanh(x @ Wcin^T) -> c_concat (row = b*T+t) --------
    for (int j = bid; j < 16384; j += GRID) {
        int rt = j >> 2, ct = j & 3;
        gemm32x64<EPI_TANH, false>(input, 0, 0, II, 0, g_WcinT, HH, bcin,
                                   outC, HH, rt * 32, ct * 64, 4, sAs, sWs);
    }
    barrier_G(++kG);

    // -------- init state --------
    if (bid < BB) {
        int b = bid;
        for (int j = tid; j < HH; j += NTHR) {
            g_c[b][j] = 0.f;
            g_h[b][j] = 0.f;
            g_com[b][j] = 0.f;
            g_com[b][HH + j] = outC[(size_t)b * TT * HH + j];
        }
        if (tid == 0) g_n[b] = 0.f;
    }
    barrier_G(++kG);

    // -------- recurrent loop --------
    for (int t = 0; t < TT; t++) {
        if (bid < 128) {
            // slot-0 on SMs 0..127: 3-layer MLP chain with light barriers
            do_a(0, bid, b1, b2, sAs, sWs);
            barrier_L(++kL);
            do_a(1, bid, b1, b2, sAs, sWs);
            barrier_L(++kL);
            do_a(2, bid, b1, b2, sAs, sWs);
        } else {
            kL += 2;                          // keep episode count uniform
            if (sm < 128) {
                // slots 1-2 on SMs 0..127: one half-gate job each (jobs 0..255)
                gate_job((sl - 1) * 128 + sm, sAs, sWs);
            } else {
                // 60 CTAs on SMs 128..147: jobs 256..383 (2 each, first 8 get a 3rd)
                int idx = sl * 20 + (sm - 128);
                gate_job(256 + 2 * idx, sAs, sWs);
                gate_job(257 + 2 * idx, sAs, sWs);
                if (idx < 8) gate_job(376 + idx, sAs, sWs);
            }
        }
        barrier_G(++kG);                      // a3 + all gate partials done

        // -------- phase U --------
        if (bid < BB) {
            int b = bid;
            float part = 0.f;
#pragma unroll
            for (int q = 0; q < 4; q++) {
                int k = tid + q * NTHR;
                float v = g_a3p[0][b][k] + g_a3p[1][b][k] + b3[k];
                part += fmaxf(v, 0.f) * W4[k];
            }
#pragma unroll
            for (int sh = 16; sh > 0; sh >>= 1)
                part += __shfl_down_sync(0xffffffffu, part, sh);
            if ((tid & 31) == 0) su[tid >> 5] = part;
            __syncthreads();
            if (tid == 0) {
                float logit = b4[0] + su[0] + su[1] + su[2] + su[3];
                float u = noise[(size_t)t * BB + b];
                float logistic = logf(u) - log1pf(-u);
                float a = sigf((logit + logistic) * 10.f);   // / TEMP
                float nold = g_n[b];
                su[8] = a;
                su[9] = nold;
                g_n[b] = nold * (1.f - a) + 1.f;
            }
            __syncthreads();
            float alpha = su[8], nold = su[9];
            float nnew = nold * (1.f - alpha) + 1.f;
#pragma unroll
            for (int u2 = 0; u2 < 2; u2++) {
                int jj = tid + u2 * NTHR;
                float c = g_c[b][jj], h = g_h[b][jj];
                float cin = outC[(size_t)b * TT * HH + (size_t)t * HH + jj];
                float gir = g_gip[0][b][jj] + g_gip[1][b][jj] + bih[jj];
                float ghr = g_ghp[0][b][jj] + g_ghp[1][b][jj] + bhh[jj];
                float giz = g_gip[0][b][HH + jj] + g_gip[1][b][HH + jj] + bih[HH + jj];
                float ghz = g_ghp[0][b][HH + jj] + g_ghp[1][b][HH + jj] + bhh[HH + jj];
                float gin = g_gip[0][b][2 * HH + jj] + g_gip[1][b][2 * HH + jj] + bih[2 * HH + jj];
                float ghn = g_ghp[0][b][2 * HH + jj] + g_ghp[1][b][2 * HH + jj] + bhh[2 * HH + jj];
                float r  = sigf(gir + ghr);
                float z  = sigf(giz + ghz);
                float ng = tanhf(gin + r * ghn);
                float hcand = (1.f - z) * ng + z * h;
                float hnew = h * (1.f - alpha) + alpha * hcand;
                float cnew = (c * nold * (1.f - alpha) + cin) / nnew;
                g_c[b][jj] = cnew;
                g_h[b][jj] = hnew;
                outH[(size_t)b * TT * HH + (size_t)t * HH + jj] = hnew;
                g_com[b][jj] = cnew;
                if (t + 1 < TT)
                    g_com[b][HH + jj] = outC[(size_t)b * TT * HH + (size_t)(t + 1) * HH + jj];
            }
        }
        barrier_G(++kG);                      // U done -> next step may start
    }

    // -------- epilogue: h_final = gru_cell(c_T, h_T) --------
    if (bid < 384) gate_job(bid, sAs, sWs);
    barrier_G(++kG);
    if (bid < BB) {
        int b = bid;
#pragma unroll
        for (int u2 = 0; u2 < 2; u2++) {
            int jj = tid + u2 * NTHR;
            float h = g_h[b][jj];
            float gir = g_gip[0][b][jj] + g_gip[1][b][jj] + bih[jj];
            float ghr = g_ghp[0][b][jj] + g_ghp[1][b][jj] + bhh[jj];
            float giz = g_gip[0][b][HH + jj] + g_gip[1][b][HH + jj] + bih[HH + jj];
            float ghz = g_ghp[0][b][HH + jj] + g_ghp[1][b][HH + jj] + bhh[HH + jj];
            float gin = g_gip[0][b][2 * HH + jj] + g_gip[1][b][2 * HH + jj] + bih[2 * HH + jj];
            float ghn = g_ghp[0][b][2 * HH + jj] + g_ghp[1][b][2 * HH + jj] + bhh[2 * HH + jj];
            float r  = sigf(gir + ghr);
            float z  = sigf(giz + ghz);
            float ng = tanhf(gin + r * ghn);
            outF[(size_t)b * HH + jj] = (1.f - z) * ng + z * h;
        }
    }

    // persist episode bases for the next launch / graph replay
    if (bid == 0 && tid == 0) {
        g_epochG = kG;
        g_epochL = kL;
    }
}

extern "C" void kernel_launch(void* const* d_in, const int* in_sizes, int n_in,
                              void* d_out, int out_size)
{
    const float* input = (const float*)d_in[0];
    const float* noise = (const float*)d_in[1];
    const float* Wcin  = (const float*)d_in[2];
    const float* bcin  = (const float*)d_in[3];
    const float* W1    = (const float*)d_in[4];
    const float* b1    = (const float*)d_in[5];
    const float* W2    = (const float*)d_in[6];
    const float* b2    = (const float*)d_in[7];
    const float* W3    = (const float*)d_in[8];
    const float* b3    = (const float*)d_in[9];
    const float* W4    = (const float*)d_in[10];
    const float* b4    = (const float*)d_in[11];
    const float* Wih   = (const float*)d_in[12];
    const float* Whh   = (const float*)d_in[13];
    const float* bih   = (const float*)d_in[14];
    const float* bhh   = (const float*)d_in[15];

    float* outC = (float*)d_out;                   // c_concat [B,T,H]
    float* outH = outC + (size_t)BB * TT * HH;     // h_concat [B,T,H]
    float* outF = outH + (size_t)BB * TT * HH;     // h_final  [B,H]

    rnn_persistent<<<GRID, NTHR>>>(input, noise, Wcin, bcin, W1, b1, W2, b2,
                                   W3, b3, W4, b4, Wih, Whh, bih, bhh,
                                   outC, outH, outF);
}

// round 13
// speedup vs baseline: 1.4708x; 1.4114x over previous
#include <cuda_runtime.h>
#include <math.h>

#define BB 256
#define TT 512
#define II 128
#define HH 256
#define H2 512
#define H3 768
#define SMS 148
#define GRID 296
#define NTHR 128
#define GSTRIDE (GRID * NTHR)

typedef unsigned long long ull;

// gemm8x8 smem geometry: BK=16
#define A_PITCH 34                 // ull per k-row (32 pairs + 2 pad, 16B-aligned)
#define W_PITCH 132                // f32 per k-row (128 cols + 4 pad)
#define ABUF (16 * A_PITCH)        // 544 ull
#define WBUF (16 * W_PITCH)        // 2112 f32

enum { EPI_RAW = 0, EPI_TANH = 2 };

// ---------------- persistent device scratch (no allocations) ----------------
__device__ float g_W1t[H2 * H2];     // transposed: Wt[k][n] = W[n][k]
__device__ float g_W2t[H2 * H2];
__device__ float g_W3t[H2 * H2];
__device__ float g_WihT[HH * H3];
__device__ float g_WhhT[HH * H3];
__device__ float g_WcinT[II * HH];

__device__ float g_com[BB][H2];      // [c | c_in_t]
__device__ float g_a1p[4][BB][H2];   // MLP K-split-4 partials
__device__ float g_a2p[4][BB][H2];
__device__ float g_a3p[4][BB][H2];
__device__ float g_gip[2][BB][H3];   // gate K-split-2 partials (no bias)
__device__ float g_ghp[2][BB][H3];
__device__ float g_c[BB][HH];
__device__ float g_h[BB][HH];
__device__ float g_n[BB];

// ---------------- hierarchical barriers (monotonic, replay-safe) ----------------
__device__ unsigned g_cntG[32 * 32];
__device__ unsigned g_cntL[16 * 32];
__device__ volatile unsigned g_genG;
__device__ volatile unsigned g_genL;
__device__ unsigned g_epochG, g_epochL;

__device__ __forceinline__ void barrier_G(unsigned k)
{
    __syncthreads();
    if (threadIdx.x == 0) {
        __threadfence();
        atomicAdd(&g_cntG[(blockIdx.x & 31) << 5], 1u);
        if (blockIdx.x == 0) {
            unsigned long long need = (unsigned long long)k * GRID;
            for (;;) {
                unsigned long long s = 0;
#pragma unroll
                for (int i = 0; i < 32; i++)
                    s += ((volatile unsigned*)g_cntG)[i << 5];
                if (s >= need) break;
                __nanosleep(64);
            }
            __threadfence();
            g_genG = k;
        } else {
            while (g_genG < k) __nanosleep(96);
        }
        __threadfence();
    }
    __syncthreads();
}

// light barrier: bids 0..147 participate
__device__ __forceinline__ void barrier_L(unsigned k)
{
    __syncthreads();
    if (threadIdx.x == 0) {
        __threadfence();
        atomicAdd(&g_cntL[(blockIdx.x & 15) << 5], 1u);
        if (blockIdx.x == 0) {
            unsigned long long need = (unsigned long long)k * 148u;
            for (;;) {
                unsigned long long s = 0;
#pragma unroll
                for (int i = 0; i < 16; i++)
                    s += ((volatile unsigned*)g_cntL)[i << 5];
                if (s >= need) break;
                __nanosleep(32);
            }
            __threadfence();
            g_genL = k;
        } else {
            while (g_genL < k) __nanosleep(64);
        }
        __threadfence();
    }
    __syncthreads();
}

__device__ __forceinline__ float sigf(float x) { return 1.f / (1.f + expf(-x)); }

__device__ __forceinline__ ull pack2(float x, float y) {
    ull r; asm("mov.b64 %0,{%1,%2};" : "=l"(r) : "f"(x), "f"(y)); return r;
}
__device__ __forceinline__ void unpack2(ull v, float& x, float& y) {
    asm("mov.b64 {%0,%1},%2;" : "=f"(x), "=f"(y) : "l"(v));
}
__device__ __forceinline__ void fma2(ull& d, ull a, ull b) {
    asm("fma.rn.f32x2 %0, %1, %2, %0;" : "+l"(d) : "l"(a), "l"(b));
}

// -------------------------------------------------------------------------
// 64x128 output tile, K=128 (8 k-tiles of 16), 128 threads, per-thread 8x8.
// A staged as NATURAL row-pair ulls (no smem dup); W staged raw.
// Per warp-kk: 4x LDS.128 (64B/lane) + 8 reg-dups (ALU) + 32 FFMA2.
// B/MAC = 1.0 -> crossbar and fma pipes balanced.
// NSRC=4: A = relu(sum of 4 partials + kb) computed during prefetch.
// -------------------------------------------------------------------------
template<int EPI, int NSRC>
__device__ __noinline__ void gemm8x8(
    const float* __restrict__ A0, size_t srcStride, const float* __restrict__ kb,
    int lda, int koff,
    const float* __restrict__ Wt, int ldw,
    const float* __restrict__ bias,
    float* __restrict__ C, int ldc,
    int rowBase, int colBase,
    ull* __restrict__ As, float* __restrict__ Ws)
{
    const int tid = threadIdx.x;
    const int tx  = tid & 15;       // col group: cols 4tx..4tx+3 and 64+4tx..
    const int ty  = tid >> 4;       // row group: rows 8ty..8ty+7
    const int p   = tid >> 2;       // A loader: pair 0..31 (rows 2p,2p+1)
    const int kq  = tid & 3;        // A loader: k-quad
    const int wk  = tid >> 3;       // W loader: k row 0..15
    const int wc  = tid & 7;        // W loader: col lane

    ull acc[4][8];
#pragma unroll
    for (int i = 0; i < 4; i++)
#pragma unroll
        for (int j = 0; j < 8; j++) acc[i][j] = 0;

    float4 x0, x1, wv0, wv1, wv2, wv3;

#define LOAD_T(kt)                                                             \
    {                                                                          \
        int kg = koff + (kt) * 16 + 4 * kq;                                    \
        const float* ap = A0 + (size_t)(rowBase + 2 * p) * lda + kg;           \
        x0 = *(const float4*)ap;                                               \
        x1 = *(const float4*)(ap + lda);                                       \
        if (NSRC == 4) {                                                       \
            _Pragma("unroll")                                                  \
            for (int s = 1; s < 4; s++) {                                      \
                const float* bp = ap + s * srcStride;                          \
                float4 u0 = *(const float4*)bp;                                \
                float4 u1 = *(const float4*)(bp + lda);                        \
                x0.x += u0.x; x0.y += u0.y; x0.z += u0.z; x0.w += u0.w;        \
                x1.x += u1.x; x1.y += u1.y; x1.z += u1.z; x1.w += u1.w;        \
            }                                                                  \
            float4 bb = *(const float4*)(kb + kg);                             \
            x0.x = fmaxf(x0.x + bb.x, 0.f);                                    \
            x0.y = fmaxf(x0.y + bb.y, 0.f);                                    \
            x0.z = fmaxf(x0.z + bb.z, 0.f);                                    \
            x0.w = fmaxf(x0.w + bb.w, 0.f);                                    \
            x1.x = fmaxf(x1.x + bb.x, 0.f);                                    \
            x1.y = fmaxf(x1.y + bb.y, 0.f);                                    \
            x1.z = fmaxf(x1.z + bb.z, 0.f);                                    \
            x1.w = fmaxf(x1.w + bb.w, 0.f);                                    \
        }                                                                      \
        const float* wp = Wt + (size_t)(koff + (kt) * 16 + wk) * ldw           \
                          + colBase + 4 * wc;                                  \
        wv0 = *(const float4*)wp;                                              \
        wv1 = *(const float4*)(wp + 32);                                       \
        wv2 = *(const float4*)(wp + 64);                                       \
        wv3 = *(const float4*)(wp + 96);                                       \
    }

#define STORE_T(bi)                                                            \
    {                                                                          \
        ull* as = As + (bi) * ABUF;                                            \
        as[(4 * kq + 0) * A_PITCH + p] = pack2(x0.x, x1.x);                    \
        as[(4 * kq + 1) * A_PITCH + p] = pack2(x0.y, x1.y);                    \
        as[(4 * kq + 2) * A_PITCH + p] = pack2(x0.z, x1.z);                    \
        as[(4 * kq + 3) * A_PITCH + p] = pack2(x0.w, x1.w);                    \
        float* ws = Ws + (bi) * WBUF;                                          \
        *(float4*)(ws + wk * W_PITCH + 4 * wc)      = wv0;                     \
        *(float4*)(ws + wk * W_PITCH + 4 * wc + 32) = wv1;                     \
        *(float4*)(ws + wk * W_PITCH + 4 * wc + 64) = wv2;                     \
        *(float4*)(ws + wk * W_PITCH + 4 * wc + 96) = wv3;                     \
    }

    LOAD_T(0);
    STORE_T(0);
    __syncthreads();

#pragma unroll 1
    for (int kt = 0; kt < 8; kt++) {
        if (kt < 7) LOAD_T(kt + 1);
        {
            const ull*   as = As + (kt & 1) * ABUF;
            const float* ws = Ws + (kt & 1) * WBUF;
#pragma unroll
            for (int kk = 0; kk < 16; kk++) {
                ulonglong2 aA = *(const ulonglong2*)&as[kk * A_PITCH + 4 * ty];
                ulonglong2 aB = *(const ulonglong2*)&as[kk * A_PITCH + 4 * ty + 2];
                float4 wa = *(const float4*)&ws[kk * W_PITCH + 4 * tx];
                float4 wb = *(const float4*)&ws[kk * W_PITCH + 64 + 4 * tx];
                ull w0 = pack2(wa.x, wa.x), w1 = pack2(wa.y, wa.y);
                ull w2 = pack2(wa.z, wa.z), w3 = pack2(wa.w, wa.w);
                ull w4 = pack2(wb.x, wb.x), w5 = pack2(wb.y, wb.y);
                ull w6 = pack2(wb.z, wb.z), w7 = pack2(wb.w, wb.w);
                fma2(acc[0][0], aA.x, w0); fma2(acc[0][1], aA.x, w1);
                fma2(acc[0][2], aA.x, w2); fma2(acc[0][3], aA.x, w3);
                fma2(acc[0][4], aA.x, w4); fma2(acc[0][5], aA.x, w5);
                fma2(acc[0][6], aA.x, w6); fma2(acc[0][7], aA.x, w7);
                fma2(acc[1][0], aA.y, w0); fma2(acc[1][1], aA.y, w1);
                fma2(acc[1][2], aA.y, w2); fma2(acc[1][3], aA.y, w3);
                fma2(acc[1][4], aA.y, w4); fma2(acc[1][5], aA.y, w5);
                fma2(acc[1][6], aA.y, w6); fma2(acc[1][7], aA.y, w7);
                fma2(acc[2][0], aB.x, w0); fma2(acc[2][1], aB.x, w1);
                fma2(acc[2][2], aB.x, w2); fma2(acc[2][3], aB.x, w3);
                fma2(acc[2][4], aB.x, w4); fma2(acc[2][5], aB.x, w5);
                fma2(acc[2][6], aB.x, w6); fma2(acc[2][7], aB.x, w7);
                fma2(acc[3][0], aB.y, w0); fma2(acc[3][1], aB.y, w1);
                fma2(acc[3][2], aB.y, w2); fma2(acc[3][3], aB.y, w3);
                fma2(acc[3][4], aB.y, w4); fma2(acc[3][5], aB.y, w5);
                fma2(acc[3][6], aB.y, w6); fma2(acc[3][7], aB.y, w7);
            }
        }
        if (kt < 7) STORE_T((kt + 1) & 1);
        __syncthreads();
    }
#undef LOAD_T
#undef STORE_T

    // epilogue: acc[pp][j] = rows (8ty+2pp, 8ty+2pp+1), col j<4: 4tx+j else 64+4tx+j-4
    float4 b0, b1;
    if (EPI == EPI_TANH) {
        b0 = *(const float4*)(bias + colBase + 4 * tx);
        b1 = *(const float4*)(bias + colBase + 64 + 4 * tx);
    }
#pragma unroll
    for (int pp = 0; pp < 4; pp++) {
        float e[8], o[8];
#pragma unroll
        for (int j = 0; j < 8; j++) unpack2(acc[pp][j], e[j], o[j]);
        float4 elo = make_float4(e[0], e[1], e[2], e[3]);
        float4 ehi = make_float4(e[4], e[5], e[6], e[7]);
        float4 olo = make_float4(o[0], o[1], o[2], o[3]);
        float4 ohi = make_float4(o[4], o[5], o[6], o[7]);
        if (EPI == EPI_TANH) {
            elo.x = tanhf(elo.x + b0.x); elo.y = tanhf(elo.y + b0.y);
            elo.z = tanhf(elo.z + b0.z); elo.w = tanhf(elo.w + b0.w);
            ehi.x = tanhf(ehi.x + b1.x); ehi.y = tanhf(ehi.y + b1.y);
            ehi.z = tanhf(ehi.z + b1.z); ehi.w = tanhf(ehi.w + b1.w);
            olo.x = tanhf(olo.x + b0.x); olo.y = tanhf(olo.y + b0.y);
            olo.z = tanhf(olo.z + b0.z); olo.w = tanhf(olo.w + b0.w);
            ohi.x = tanhf(ohi.x + b1.x); ohi.y = tanhf(ohi.y + b1.y);
            ohi.z = tanhf(ohi.z + b1.z); ohi.w = tanhf(ohi.w + b1.w);
        }
        float* c0 = C + (size_t)(rowBase + 8 * ty + 2 * pp) * ldc + colBase + 4 * tx;
        float* c1 = c0 + ldc;
        *(float4*)c0        = elo;
        *(float4*)(c0 + 64) = ehi;
        *(float4*)c1        = olo;
        *(float4*)(c1 + 64) = ohi;
    }
}

// MLP job j in [0,64): rt(0..3) x ct(0..3) x kh(0..3); 64x128 tile, K=128
__device__ __forceinline__ void mlp_job(int ph, int j, const float* b1,
                                        const float* b2, ull* As, float* Ws)
{
    int rt = j >> 4, ct = (j >> 2) & 3, kh = j & 3;
    int rb = rt * 64, cb = ct * 128, ko = kh * 128;
    if (ph == 0)
        gemm8x8<EPI_RAW, 1>(&g_com[0][0], 0, 0, H2, ko, g_W1t, H2, 0,
                            &g_a1p[kh][0][0], H2, rb, cb, As, Ws);
    else if (ph == 1)
        gemm8x8<EPI_RAW, 4>(&g_a1p[0][0][0], (size_t)BB * H2, b1, H2, ko,
                            g_W2t, H2, 0, &g_a2p[kh][0][0], H2, rb, cb, As, Ws);
    else
        gemm8x8<EPI_RAW, 4>(&g_a2p[0][0][0], (size_t)BB * H2, b2, H2, ko,
                            g_W3t, H2, 0, &g_a3p[kh][0][0], H2, rb, cb, As, Ws);
}

// gate job g in [0,96): g<48 gi else gh; q -> rt(0..3) x ct(0..5) x kh(0..1)
__device__ __forceinline__ void gate_job(int g, ull* As, float* Ws)
{
    bool is_gi = g < 48;
    int q = is_gi ? g : g - 48;
    int rt = q / 12, rem = q % 12, ct = rem >> 1, kh = rem & 1;
    int rb = rt * 64, cb = ct * 128, ko = kh * 128;
    if (is_gi)
        gemm8x8<EPI_RAW, 1>(&g_c[0][0], 0, 0, HH, ko, g_WihT, H3, 0,
                            &g_gip[kh][0][0], H3, rb, cb, As, Ws);
    else
        gemm8x8<EPI_RAW, 1>(&g_h[0][0], 0, 0, HH, ko, g_WhhT, H3, 0,
                            &g_ghp[kh][0][0], H3, rb, cb, As, Ws);
}

// =========================== persistent megakernel ===========================
__global__ void __launch_bounds__(NTHR, 2)
rnn_persistent(const float* __restrict__ input, const float* __restrict__ noise,
               const float* __restrict__ Wcin, const float* __restrict__ bcin,
               const float* __restrict__ W1, const float* __restrict__ b1,
               const float* __restrict__ W2, const float* __restrict__ b2,
               const float* __restrict__ W3, const float* __restrict__ b3,
               const float* __restrict__ W4, const float* __restrict__ b4,
               const float* __restrict__ Wih, const float* __restrict__ Whh,
               const float* __restrict__ bih, const float* __restrict__ bhh,
               float* __restrict__ outC, float* __restrict__ outH,
               float* __restrict__ outF)
{
    __shared__ __align__(16) ull   sAs[2 * ABUF];
    __shared__ __align__(16) float sWs[2 * WBUF];
    __shared__ float su[16];

    const int bid = blockIdx.x;
    const int tid = threadIdx.x;
    const int gt  = bid * NTHR + tid;

    unsigned kG = g_epochG;
    unsigned kL = g_epochL;

    // -------- weight transposes (once per launch) --------
    for (int i = gt; i < H2 * H2; i += GSTRIDE) {
        int k = i / H2, n = i % H2;
        g_W1t[i] = W1[(size_t)n * H2 + k];
        g_W2t[i] = W2[(size_t)n * H2 + k];
        g_W3t[i] = W3[(size_t)n * H2 + k];
    }
    for (int i = gt; i < HH * H3; i += GSTRIDE) {
        int k = i / H3, n = i % H3;
        g_WihT[i] = Wih[(size_t)n * HH + k];
        g_WhhT[i] = Whh[(size_t)n * HH + k];
    }
    for (int i = gt; i < II * HH; i += GSTRIDE) {
        int k = i / HH, n = i % HH;
        g_WcinT[i] = Wcin[(size_t)n * II + k];
    }
    barrier_G(++kG);

    // -------- prologue: c_in = tanh(x @ Wcin^T) -> c_concat (row = b*T+t) --------
    for (int j = bid; j < 4096; j += GRID) {
        int rt = j >> 1, ct = j & 1;
        gemm8x8<EPI_TANH, 1>(input, 0, 0, II, 0, g_WcinT, HH, bcin,
                             outC, HH, rt * 64, ct * 128, sAs, sWs);
    }
    barrier_G(++kG);

    // -------- init state --------
    if (bid < BB) {
        int b = bid;
        for (int j = tid; j < HH; j += NTHR) {
            g_c[b][j] = 0.f;
            g_h[b][j] = 0.f;
            g_com[b][j] = 0.f;
            g_com[b][HH + j] = outC[(size_t)b * TT * HH + j];
        }
        if (tid == 0) g_n[b] = 0.f;
    }
    barrier_G(++kG);

    // -------- recurrent loop --------
    for (int t = 0; t < TT; t++) {
        if (bid < 148) {
            // ph0: a1 (64 jobs) + gates 0..83  -> exactly 1 job per SM
            if (bid < 64) mlp_job(0, bid, b1, b2, sAs, sWs);
            else          gate_job(bid - 64, sAs, sWs);
            barrier_L(++kL);
            // ph1: a2 (64 jobs) + gates 84..95
            if (bid < 64)      mlp_job(1, bid, b1, b2, sAs, sWs);
            else if (bid < 76) gate_job(84 + (bid - 64), sAs, sWs);
            barrier_L(++kL);
            // ph2: a3 (64 jobs)
            if (bid < 64) mlp_job(2, bid, b1, b2, sAs, sWs);
        } else {
            kL += 2;
        }
        barrier_G(++kG);                      // a3 + all gate partials done

        // -------- phase U --------
        if (bid < BB) {
            int b = bid;
            float part = 0.f;
#pragma unroll
            for (int q = 0; q < 4; q++) {
                int k = tid + q * NTHR;
                float v = g_a3p[0][b][k] + g_a3p[1][b][k] + g_a3p[2][b][k]
                        + g_a3p[3][b][k] + b3[k];
                part += fmaxf(v, 0.f) * W4[k];
            }
#pragma unroll
            for (int sh = 16; sh > 0; sh >>= 1)
                part += __shfl_down_sync(0xffffffffu, part, sh);
            if ((tid & 31) == 0) su[tid >> 5] = part;
            __syncthreads();
            if (tid == 0) {
                float logit = b4[0] + su[0] + su[1] + su[2] + su[3];
                float u = noise[(size_t)t * BB + b];
                float logistic = logf(u) - log1pf(-u);
                float a = sigf((logit + logistic) * 10.f);   // / TEMP
                float nold = g_n[b];
                su[8] = a;
                su[9] = nold;
                g_n[b] = nold * (1.f - a) + 1.f;
            }
            __syncthreads();
            float alpha = su[8], nold = su[9];
            float nnew = nold * (1.f - alpha) + 1.f;
#pragma unroll
            for (int u2 = 0; u2 < 2; u2++) {
                int jj = tid + u2 * NTHR;
                float c = g_c[b][jj], h = g_h[b][jj];
                float cin = outC[(size_t)b * TT * HH + (size_t)t * HH + jj];
                float gir = g_gip[0][b][jj] + g_gip[1][b][jj] + bih[jj];
                float ghr = g_ghp[0][b][jj] + g_ghp[1][b][jj] + bhh[jj];
                float giz = g_gip[0][b][HH + jj] + g_gip[1][b][HH + jj] + bih[HH + jj];
                float ghz = g_ghp[0][b][HH + jj] + g_ghp[1][b][HH + jj] + bhh[HH + jj];
                float gin = g_gip[0][b][2 * HH + jj] + g_gip[1][b][2 * HH + jj] + bih[2 * HH + jj];
                float ghn = g_ghp[0][b][2 * HH + jj] + g_ghp[1][b][2 * HH + jj] + bhh[2 * HH + jj];
                float r  = sigf(gir + ghr);
                float z  = sigf(giz + ghz);
                float ng = tanhf(gin + r * ghn);
                float hcand = (1.f - z) * ng + z * h;
                float hnew = h * (1.f - alpha) + alpha * hcand;
                float cnew = (c * nold * (1.f - alpha) + cin) / nnew;
                g_c[b][jj] = cnew;
                g_h[b][jj] = hnew;
                outH[(size_t)b * TT * HH + (size_t)t * HH + jj] = hnew;
                g_com[b][jj] = cnew;
                if (t + 1 < TT)
                    g_com[b][HH + jj] = outC[(size_t)b * TT * HH + (size_t)(t + 1) * HH + jj];
            }
        }
        barrier_G(++kG);                      // U done -> next step may start
    }

    // -------- epilogue: h_final = gru_cell(c_T, h_T) --------
    if (bid < 96) gate_job(bid, sAs, sWs);
    barrier_G(++kG);
    if (bid < BB) {
        int b = bid;
#pragma unroll
        for (int u2 = 0; u2 < 2; u2++) {
            int jj = tid + u2 * NTHR;
            float h = g_h[b][jj];
            float gir = g_gip[0][b][jj] + g_gip[1][b][jj] + bih[jj];
            float ghr = g_ghp[0][b][jj] + g_ghp[1][b][jj] + bhh[jj];
            float giz = g_gip[0][b][HH + jj] + g_gip[1][b][HH + jj] + bih[HH + jj];
            float ghz = g_ghp[0][b][HH + jj] + g_ghp[1][b][HH + jj] + bhh[HH + jj];
            float gin = g_gip[0][b][2 * HH + jj] + g_gip[1][b][2 * HH + jj] + bih[2 * HH + jj];
            float ghn = g_ghp[0][b][2 * HH + jj] + g_ghp[1][b][2 * HH + jj] + bhh[2 * HH + jj];
            float r  = sigf(gir + ghr);
            float z  = sigf(giz + ghz);
            float ng = tanhf(gin + r * ghn);
            outF[(size_t)b * HH + jj] = (1.f - z) * ng + z * h;
        }
    }

    // persist episode bases for the next launch / graph replay
    if (bid == 0 && tid == 0) {
        g_epochG = kG;
        g_epochL = kL;
    }
}

extern "C" void kernel_launch(void* const* d_in, const int* in_sizes, int n_in,
                              void* d_out, int out_size)
{
    const float* input = (const float*)d_in[0];
    const float* noise = (const float*)d_in[1];
    const float* Wcin  = (const float*)d_in[2];
    const float* bcin  = (const float*)d_in[3];
    const float* W1    = (const float*)d_in[4];
    const float* b1    = (const float*)d_in[5];
    const float* W2    = (const float*)d_in[6];
    const float* b2    = (const float*)d_in[7];
    const float* W3    = (const float*)d_in[8];
    const float* b3    = (const float*)d_in[9];
    const float* W4    = (const float*)d_in[10];
    const float* b4    = (const float*)d_in[11];
    const float* Wih   = (const float*)d_in[12];
    const float* Whh   = (const float*)d_in[13];
    const float* bih   = (const float*)d_in[14];
    const float* bhh   = (const float*)d_in[15];

    float* outC = (float*)d_out;                   // c_concat [B,T,H]
    float* outH = outC + (size_t)BB * TT * HH;     // h_concat [B,T,H]
    float* outF = outH + (size_t)BB * TT * HH;     // h_final  [B,H]

    rnn_persistent<<<GRID, NTHR>>>(input, noise, Wcin, bcin, W1, b1, W2, b2,
                                   W3, b3, W4, b4, Wih, Whh, bih, bhh,
                                   outC, outH, outF);
}